// round 5
// baseline (speedup 1.0000x reference)
#include <cuda_runtime.h>
#include <cuda_bf16.h>
#include <math.h>

#define BATCH 32
#define HDIM 112
#define WDIM 112
#define CDIM 192
#define HW (HDIM*WDIM)          // 12544
#define C4 (CDIM/4)             // 48

// ---------------- scratch (device globals; no allocation) ----------------
__device__ float    g_sum[BATCH*CDIM];          // spatial sum per (b,c)
__device__ unsigned g_maxu[BATCH*CDIM];         // spatial max per (b,c), ordered-uint
__device__ float    g_scale[BATCH*CDIM];        // fused se*channel_att per (b,c)
__device__ float    g_sp[BATCH*HW*2];           // per-pixel {avg_c, max_c}
__device__ float    g_sa[BATCH*HW];             // spatial attention per pixel

// monotone float -> unsigned mapping for atomicMax
__device__ __forceinline__ unsigned f2u_ord(float f) {
    unsigned u = __float_as_uint(f);
    return (u & 0x80000000u) ? ~u : (u | 0x80000000u);
}
__device__ __forceinline__ float u2f_ord(unsigned u) {
    return (u & 0x80000000u) ? __uint_as_float(u & 0x7fffffffu) : __uint_as_float(~u);
}
__device__ __forceinline__ float sigm(float v) { return 1.0f / (1.0f + expf(-v)); }
__device__ __forceinline__ float swishf(float v) { return v * sigm(v); }

// ---------------- kernel 0: init accumulators ----------------
__global__ void k_init() {
    int i = blockIdx.x * 256 + threadIdx.x;
    if (i < BATCH*CDIM) { g_sum[i] = 0.0f; g_maxu[i] = 0u; }
}

// ---------------- kernel 1: fused pools (one pass over x) ----------------
// grid (H, B), block 256 (8 warps). Each block = one row of 112 pixels.
// Per pixel a warp loads 96 float2 (coalesced), accumulating:
//   - per-lane channel sum/max (6 channels per lane)  -> spatial pool
//   - warp-shuffle sum/max over 192 channels          -> per-pixel channel pool
__global__ void k_pool(const float* __restrict__ x) {
    int b = blockIdx.y, h = blockIdx.x;
    int warp = threadIdx.x >> 5, lane = threadIdx.x & 31;

    __shared__ float    s_sum[CDIM];
    __shared__ unsigned s_max[CDIM];
    if (threadIdx.x < CDIM) { s_sum[threadIdx.x] = 0.0f; s_max[threadIdx.x] = 0u; }
    __syncthreads();

    float csum[6] = {0.f,0.f,0.f,0.f,0.f,0.f};
    float cmax[6] = {-3.4e38f,-3.4e38f,-3.4e38f,-3.4e38f,-3.4e38f,-3.4e38f};

    const float* xrow = x + (size_t)(b*HW + h*WDIM) * CDIM;

    for (int p = warp; p < WDIM; p += 8) {
        const float2* px = (const float2*)(xrow + p*CDIM);
        float psum = 0.0f, pmax = -3.4e38f;
        #pragma unroll
        for (int j = 0; j < 3; j++) {
            float2 v = px[lane + 32*j];
            csum[2*j]   += v.x;  csum[2*j+1] += v.y;
            cmax[2*j]   = fmaxf(cmax[2*j],   v.x);
            cmax[2*j+1] = fmaxf(cmax[2*j+1], v.y);
            psum += v.x + v.y;
            pmax = fmaxf(pmax, fmaxf(v.x, v.y));
        }
        #pragma unroll
        for (int o = 16; o > 0; o >>= 1) {
            psum += __shfl_xor_sync(0xffffffffu, psum, o);
            pmax = fmaxf(pmax, __shfl_xor_sync(0xffffffffu, pmax, o));
        }
        if (lane == 0) {
            int pix = b*HW + h*WDIM + p;
            g_sp[pix*2]   = psum * (1.0f/192.0f);
            g_sp[pix*2+1] = pmax;
        }
    }

    #pragma unroll
    for (int j = 0; j < 3; j++) {
        int c = 2*(lane + 32*j);
        atomicAdd(&s_sum[c],   csum[2*j]);
        atomicAdd(&s_sum[c+1], csum[2*j+1]);
        atomicMax(&s_max[c],   f2u_ord(cmax[2*j]));
        atomicMax(&s_max[c+1], f2u_ord(cmax[2*j+1]));
    }
    __syncthreads();
    if (threadIdx.x < CDIM) {
        atomicAdd(&g_sum[b*CDIM + threadIdx.x], s_sum[threadIdx.x]);
        atomicMax(&g_maxu[b*CDIM + threadIdx.x], s_max[threadIdx.x]);
    }
}

// ---------------- kernel 2: SE + CBAM-channel MLPs, fused scale ----------------
// grid B, block 192
__global__ void k_mlp(const float* __restrict__ se_w1, const float* __restrict__ se_b1,
                      const float* __restrict__ se_w2, const float* __restrict__ se_b2,
                      const float* __restrict__ mlp_w1, const float* __restrict__ mlp_b1,
                      const float* __restrict__ mlp_w2, const float* __restrict__ mlp_b2) {
    int b = blockIdx.x, t = threadIdx.x;
    __shared__ float avg[CDIM], mx[CDIM], hse[12], ha[24], hm[24];

    avg[t] = g_sum[b*CDIM + t] * (1.0f/(float)HW);
    mx[t]  = u2f_ord(g_maxu[b*CDIM + t]);
    __syncthreads();

    if (t < 12) {                          // SE hidden (192 -> 12), swish
        float a = se_b1[t];
        for (int c = 0; c < CDIM; c++) a += avg[c] * se_w1[c*12 + t];
        hse[t] = swishf(a);
    } else if (t >= 32 && t < 56) {        // CBAM hidden (192 -> 24) for avg & max
        int j = t - 32;
        float a = mlp_b1[j], m = mlp_b1[j];
        for (int c = 0; c < CDIM; c++) {
            float w = mlp_w1[c*24 + j];
            a += avg[c]*w; m += mx[c]*w;
        }
        ha[j] = swishf(a); hm[j] = swishf(m);
    }
    __syncthreads();

    float s = se_b2[t];
    #pragma unroll
    for (int j = 0; j < 12; j++) s += hse[j] * se_w2[j*CDIM + t];
    float catt = 2.0f * mlp_b2[t];
    #pragma unroll
    for (int j = 0; j < 24; j++) catt += (ha[j] + hm[j]) * mlp_w2[j*CDIM + t];

    g_scale[b*CDIM + t] = sigm(s) * sigm(catt);
}

// ---------------- kernel 3: 7x7x2 conv + sigmoid -> spatial attention ----------------
// grid (H, B), block 112 (one output pixel per thread)
__global__ void k_conv(const float* __restrict__ conv_k, const float* __restrict__ conv_b) {
    int b = blockIdx.y, h = blockIdx.x, w = threadIdx.x;
    __shared__ float tile[7][WDIM+6][2];   // rows h-3..h+3, cols padded -3..114
    __shared__ float kk[98];
    __shared__ float kb;

    for (int i = threadIdx.x; i < 7*(WDIM+6)*2; i += WDIM) {
        int kh = i / ((WDIM+6)*2);
        int rem = i - kh*((WDIM+6)*2);
        int ww = rem >> 1, ch = rem & 1;
        int gh = h + kh - 3, gw = ww - 3;
        float v = 0.0f;
        if (gh >= 0 && gh < HDIM && gw >= 0 && gw < WDIM)
            v = g_sp[(size_t)(b*HW + gh*WDIM + gw)*2 + ch];
        tile[kh][ww][ch] = v;
    }
    if (threadIdx.x < 98) kk[threadIdx.x] = conv_k[threadIdx.x];
    if (threadIdx.x == 0) kb = conv_b[0];
    __syncthreads();

    float acc = kb;
    #pragma unroll
    for (int kh = 0; kh < 7; kh++)
        #pragma unroll
        for (int kw = 0; kw < 7; kw++) {
            acc += tile[kh][w+kw][0] * kk[(kh*7+kw)*2]
                 + tile[kh][w+kw][1] * kk[(kh*7+kw)*2 + 1];
        }
    g_sa[b*HW + h*WDIM + w] = sigm(acc);
}

// ---------------- kernel 4: elementwise apply (float4) ----------------
// grid (H, B), block (48, 4): tid.x = c4 (scale hoisted), tid.y strides pixels
__global__ void k_apply(const float* __restrict__ x, float* __restrict__ out) {
    int b = blockIdx.y, h = blockIdx.x;
    int c4 = threadIdx.x, ty = threadIdx.y;

    float4 sc = ((const float4*)(g_scale + b*CDIM))[c4];
    const float4* xp = (const float4*)x + (size_t)(b*HW + h*WDIM) * C4;
    float4* op = (float4*)out + (size_t)(b*HW + h*WDIM) * C4;
    const float* sarow = g_sa + b*HW + h*WDIM;

    #pragma unroll 4
    for (int p = ty; p < WDIM; p += 4) {
        float s = sarow[p];
        float4 v = xp[p*C4 + c4];
        v.x *= sc.x * s; v.y *= sc.y * s;
        v.z *= sc.z * s; v.w *= sc.w * s;
        op[p*C4 + c4] = v;
    }
}

// ---------------- launch ----------------
extern "C" void kernel_launch(void* const* d_in, const int* in_sizes, int n_in,
                              void* d_out, int out_size) {
    const float* x      = (const float*)d_in[0];
    const float* se_w1  = (const float*)d_in[1];
    const float* se_b1  = (const float*)d_in[2];
    const float* se_w2  = (const float*)d_in[3];
    const float* se_b2  = (const float*)d_in[4];
    const float* mlp_w1 = (const float*)d_in[5];
    const float* mlp_b1 = (const float*)d_in[6];
    const float* mlp_w2 = (const float*)d_in[7];
    const float* mlp_b2 = (const float*)d_in[8];
    const float* conv_k = (const float*)d_in[9];
    const float* conv_b = (const float*)d_in[10];
    float* out = (float*)d_out;

    k_init<<<(BATCH*CDIM + 255)/256, 256>>>();
    k_pool<<<dim3(HDIM, BATCH), 256>>>(x);
    k_mlp<<<BATCH, CDIM>>>(se_w1, se_b1, se_w2, se_b2, mlp_w1, mlp_b1, mlp_w2, mlp_b2);
    k_conv<<<dim3(HDIM, BATCH), WDIM>>>(conv_k, conv_b);
    k_apply<<<dim3(HDIM, BATCH), dim3(C4, 4)>>>(x, out);
}